// round 9
// baseline (speedup 1.0000x reference)
#include <cuda_runtime.h>
#include <cuda_bf16.h>
#include <math.h>
#include <stdint.h>

#define T_STEPS 1024
#define NCTA 128
#define PS 584    // partials per-ksplit stride (floats): 32 rows * 18 + 8

// -------- packed fp32x2 helpers --------
__device__ __forceinline__ unsigned long long pack2(float x) {
    unsigned long long r; asm("mov.b64 %0, {%1, %1};" : "=l"(r) : "f"(x)); return r;
}
__device__ __forceinline__ void fma2(unsigned long long &d, unsigned long long a, unsigned long long b) {
    asm("fma.rn.f32x2 %0, %1, %2, %0;" : "+l"(d) : "l"(a), "l"(b));
}

// -------- scratch (static device globals) --------
__device__ float g_xproj[(size_t)16384 * 4096];       // 256 MB (layer-0 xproj)
__device__ float g_hbuf0[2][16384];                   // h0 double buffer [k][b]
__device__ float g_hbuf1[2][16384];                   // h1 double buffer [k][b]
__device__ int   g_flags0[NCTA * 8];
__device__ int   g_flags1[NCTA * 8];
__device__ unsigned int g_bar_count;
__device__ volatile unsigned int g_bar_gen;
__device__ __nv_bfloat16 g_A3[(size_t)16384 * 3072];  // 96 MB
__device__ __nv_bfloat16 g_W3[(size_t)4096 * 3072];   // 24 MB
__device__ float4 g_W1p[128 * 256 * 32];              // 16 MB  [cta][k4][lane]
__device__ float4 g_R1p[128 * 256 * 32];              // 16 MB

// -------- software grid barrier (init only; replay-safe) --------
__device__ __forceinline__ void grid_barrier() {
    __syncthreads();
    if (threadIdx.x == 0) {
        __threadfence();
        unsigned int gen = g_bar_gen;
        unsigned int t = atomicAdd(&g_bar_count, 1u);
        if (t == NCTA - 1) {
            g_bar_count = 0u;
            __threadfence();
            g_bar_gen = gen + 1u;
        } else {
            while (g_bar_gen == gen) { }
            __threadfence();
        }
    }
    __syncthreads();
}

// -------- cp.async helpers --------
__device__ __forceinline__ uint32_t smem_u32(const void* p) {
    uint32_t a;
    asm("{ .reg .u64 t; cvta.to.shared.u64 t, %1; cvt.u32.u64 %0, t; }" : "=r"(a) : "l"(p));
    return a;
}
__device__ __forceinline__ void cp16(uint32_t dst, const void* src) {
    asm volatile("cp.async.cg.shared.global [%0], [%1], 16;" :: "r"(dst), "l"(src));
}
__device__ __forceinline__ void cp_commit() { asm volatile("cp.async.commit_group;"); }
template <int N>
__device__ __forceinline__ void cp_wait() { asm volatile("cp.async.wait_group %0;" :: "n"(N)); }

// -------- mma.sync bf16 --------
__device__ __forceinline__ void mma_bf16(float* c, const uint32_t* a, uint32_t b0, uint32_t b1) {
    asm volatile(
        "mma.sync.aligned.m16n8k16.row.col.f32.bf16.bf16.f32 "
        "{%0,%1,%2,%3}, {%4,%5,%6,%7}, {%8,%9}, {%0,%1,%2,%3};"
        : "+f"(c[0]), "+f"(c[1]), "+f"(c[2]), "+f"(c[3])
        : "r"(a[0]), "r"(a[1]), "r"(a[2]), "r"(a[3]), "r"(b0), "r"(b1));
}

// ===================================================================
// split3: fp32 [M][1024] -> bf16 [M][3072] split-concat (L0 xproj prep)
// ===================================================================
__global__ __launch_bounds__(256) void split3(
    const float* __restrict__ src, __nv_bfloat16* __restrict__ dst,
    int off2, int off3, int seq_layout)
{
    size_t m = blockIdx.x;
    int k = threadIdx.x * 4;
    size_t si = seq_layout ? ((size_t)(m & 15) * 1048576 + (size_t)(m >> 4) * 1024 + k)
                           : (m * 1024 + k);
    float4 v = *(const float4*)(src + si);
    __nv_bfloat16 h0 = __float2bfloat16(v.x), h1 = __float2bfloat16(v.y);
    __nv_bfloat16 h2 = __float2bfloat16(v.z), h3 = __float2bfloat16(v.w);
    __nv_bfloat162 H0 = __halves2bfloat162(h0, h1), H1 = __halves2bfloat162(h2, h3);
    __nv_bfloat162 L0 = __halves2bfloat162(__float2bfloat16(v.x - __bfloat162float(h0)),
                                           __float2bfloat16(v.y - __bfloat162float(h1)));
    __nv_bfloat162 L1 = __halves2bfloat162(__float2bfloat16(v.z - __bfloat162float(h2)),
                                           __float2bfloat16(v.w - __bfloat162float(h3)));
    __nv_bfloat16* base = dst + m * 3072;
    *(__nv_bfloat162*)(base + k) = H0;          *(__nv_bfloat162*)(base + k + 2) = H1;
    *(__nv_bfloat162*)(base + off2 + k) = H0;   *(__nv_bfloat162*)(base + off2 + k + 2) = H1;
    *(__nv_bfloat162*)(base + off3 + k) = L0;   *(__nv_bfloat162*)(base + off3 + k + 2) = L1;
}

// ===================================================================
// prepack: M[4096][1024] -> [cta][k4][lane] float4 (lane-coalesced)
// lane r of cta: row = (r>>3)*1024 + cta*8 + (r&7)
// ===================================================================
__global__ __launch_bounds__(256) void prepack(
    const float* __restrict__ src, float4* __restrict__ dst)
{
    int idx = blockIdx.x * 256 + threadIdx.x;   // 0 .. 1M-1
    int r = idx & 31;
    int k4 = (idx >> 5) & 255;
    int cta = idx >> 13;
    int row = (r >> 3) * 1024 + cta * 8 + (r & 7);
    dst[idx] = *(const float4*)(src + (size_t)row * 1024 + k4 * 4);
}

// ===================================================================
// Phase A HMMA GEMM (layer-0 xproj) — unchanged, known good
// ===================================================================
#define BK 32
#define KIT 96
__global__ __launch_bounds__(256, 2) void hmma_gemm(const float* __restrict__ bias, int bias_off)
{
    __shared__ __align__(16) __nv_bfloat16 As[2][128 * 40];
    __shared__ __align__(16) __nv_bfloat16 Bs[2][128 * 40];

    int tid = threadIdx.x;
    int n0 = blockIdx.x * 128, m0 = blockIdx.y * 128;
    int warp = tid >> 5, lane = tid & 31;
    int wm = (warp & 1) * 64, wn = (warp >> 1) * 32;
    int g = lane >> 2, q = lane & 3;

    int srow = tid >> 1;
    int scol = (tid & 1) * 16;
    const __nv_bfloat16* gA = g_A3 + (size_t)(m0 + srow) * 3072 + scol;
    const __nv_bfloat16* gB = g_W3 + (size_t)(n0 + srow) * 3072 + scol;
    uint32_t sAd[2], sBd[2];
    sAd[0] = smem_u32(&As[0][srow * 40 + scol]);
    sAd[1] = smem_u32(&As[1][srow * 40 + scol]);
    sBd[0] = smem_u32(&Bs[0][srow * 40 + scol]);
    sBd[1] = smem_u32(&Bs[1][srow * 40 + scol]);

    float acc[4][4][4];
#pragma unroll
    for (int i = 0; i < 4; i++)
#pragma unroll
        for (int j = 0; j < 4; j++)
#pragma unroll
            for (int r = 0; r < 4; r++) acc[i][j][r] = 0.f;

    cp16(sAd[0], gA);      cp16(sAd[0] + 16, gA + 8);
    cp16(sBd[0], gB);      cp16(sBd[0] + 16, gB + 8);
    cp_commit();

    for (int c = 0; c < KIT; c++) {
        int buf = c & 1;
        if (c + 1 < KIT) {
            int nb = (c + 1) & 1;
            const __nv_bfloat16* a = gA + (c + 1) * BK;
            const __nv_bfloat16* b = gB + (c + 1) * BK;
            cp16(sAd[nb], a);      cp16(sAd[nb] + 16, a + 8);
            cp16(sBd[nb], b);      cp16(sBd[nb] + 16, b + 8);
            cp_commit();
            cp_wait<1>();
        } else {
            cp_wait<0>();
        }
        __syncthreads();

        const __nv_bfloat16* Ab = As[buf];
        const __nv_bfloat16* Bb = Bs[buf];
#pragma unroll
        for (int kk = 0; kk < 32; kk += 16) {
            uint32_t af[4][4];
#pragma unroll
            for (int i = 0; i < 4; i++) {
                const __nv_bfloat16* p = Ab + (wm + i * 16 + g) * 40 + kk + 2 * q;
                af[i][0] = *(const uint32_t*)p;
                af[i][1] = *(const uint32_t*)(p + 8 * 40);
                af[i][2] = *(const uint32_t*)(p + 8);
                af[i][3] = *(const uint32_t*)(p + 8 * 40 + 8);
            }
#pragma unroll
            for (int j = 0; j < 4; j++) {
                const __nv_bfloat16* p = Bb + (wn + j * 8 + g) * 40 + kk + 2 * q;
                uint32_t b0 = *(const uint32_t*)p;
                uint32_t b1 = *(const uint32_t*)(p + 8);
#pragma unroll
                for (int i = 0; i < 4; i++)
                    mma_bf16(acc[i][j], af[i], b0, b1);
            }
        }
        __syncthreads();
    }

#pragma unroll
    for (int j = 0; j < 4; j++) {
        int n = n0 + wn + j * 8 + 2 * q;
        float b0 = __ldg(bias + bias_off + n);
        float b1 = __ldg(bias + bias_off + n + 1);
#pragma unroll
        for (int i = 0; i < 4; i++) {
            int m = m0 + wm + i * 16 + g;
            float2 v0 = { acc[i][j][0] + b0, acc[i][j][1] + b1 };
            float2 v1 = { acc[i][j][2] + b0, acc[i][j][3] + b1 };
            *(float2*)(g_xproj + (size_t)m * 4096 + n) = v0;
            *(float2*)(g_xproj + (size_t)(m + 8) * 4096 + n) = v1;
        }
    }
}

// ===================================================================
// FUSED recurrence: L0 step t  ∥  L1 step (t-1), t = 0..1024.
// 512 threads, warp = k-split (64 k), lane = gate row.
// R0 in registers; W1/R1 streamed from L2 (prepacked, coalesced).
// Pointwise: warps 0-3 -> L0 (flag0), warps 4-7 -> L1 (flag1), parallel.
// SMEM: sH0 64K + sH1 64K + sP0/sP1 2*37.4K ~= 201KB -> 1 CTA/SM.
// ===================================================================
__global__ __launch_bounds__(512, 1) void fused_rec(
    const float* __restrict__ R0, const float* __restrict__ bias1)
{
    extern __shared__ float smem[];
    float* sH0 = smem;                  // [1024][16]
    float* sH1 = smem + 16384;          // [1024][16]
    float* sP0 = smem + 32768;          // [16][PS]
    float* sP1 = sP0 + 16 * PS;         // [16][PS]

    int tid = threadIdx.x;
    int ks = tid >> 5;
    int lane = tid & 31;
    int u_base = blockIdx.x * 8;

    if (tid == 0) { g_flags0[blockIdx.x * 8] = 0; g_flags1[blockIdx.x * 8] = 0; }
    grid_barrier();

    // ---- R0 slice into registers (once) ----
    int grow = (lane >> 3) * 1024 + u_base + (lane & 7);
    const float* rrow = R0 + (size_t)grow * 1024 + ks * 64;
    float Rreg[64];
#pragma unroll
    for (int j = 0; j < 64; j += 4) {
        float4 v = *(const float4*)(rrow + j);
        Rreg[j] = v.x; Rreg[j + 1] = v.y; Rreg[j + 2] = v.z; Rreg[j + 3] = v.w;
    }

    // zero both h buffers
    for (int i = tid; i < 32768; i += 512) smem[i] = 0.f;
    __syncthreads();

    // streamed W1/R1 pointers (coalesced: [cta][k4][lane])
    const float4* w1p = g_W1p + ((size_t)blockIdx.x * 256 + ks * 16) * 32 + lane;
    const float4* r1p = g_R1p + ((size_t)blockIdx.x * 256 + ks * 16) * 32 + lane;

    // pointwise mappings
    int pw_grp = tid >> 7;           // 0 = L0 pw (tid<128), 1 = L1 pw (128..255)
    int pl = tid & 127;
    int pb = pl & 15, pu = pl >> 4;
    float c0 = 0.f, n0v = 1.f, m0v = 0.f;   // L0 state (grp 0)
    float c1 = 0.f, n1v = 1.f, m1v = 0.f;   // L1 state (grp 1)
    float b1r[4] = {0.f, 0.f, 0.f, 0.f};
    if (pw_grp == 1) {
#pragma unroll
        for (int g = 0; g < 4; g++) b1r[g] = __ldg(bias1 + g * 1024 + u_base + pu);
    }

    const int* f0 = g_flags0 + (8 * ks + (lane & 7)) * 8;
    const int* f1 = g_flags1 + (8 * ks + (lane & 7)) * 8;

    for (int t = 0; t <= T_STEPS; t++) {
        // prefetch L0 xproj for this step
        float xpre[4];
        if (tid < 128 && t < T_STEPS) {
            const float* xp = g_xproj + ((size_t)t * 16 + pb) * 4096 + u_base + pu;
            xpre[0] = __ldg(xp);
            xpre[1] = __ldg(xp + 1024);
            xpre[2] = __ldg(xp + 2048);
            xpre[3] = __ldg(xp + 3072);
        }

        if (t > 0) {
            // wait for producers: h0_{t-1} (flag0>=t) and h1_{t-2} (flag1>=t-1)
            for (;;) {
                int a, b;
                asm volatile("ld.acquire.gpu.global.b32 %0, [%1];" : "=r"(a) : "l"(f0));
                asm volatile("ld.acquire.gpu.global.b32 %0, [%1];" : "=r"(b) : "l"(f1));
                if (__all_sync(0xffffffffu, (a >= t) && (b >= t - 1))) break;
            }
            // stage own 4KB h0 slice
            {
                const float4* s4 = (const float4*)(g_hbuf0[(t - 1) & 1]) + ks * 256 + lane;
                float4* d4 = (float4*)sH0 + ks * 256 + lane;
#pragma unroll
                for (int j = 0; j < 8; j++) d4[j * 32] = __ldcg(s4 + j * 32);
            }
            if (t >= 2) {
                const float4* s4 = (const float4*)(g_hbuf1[(t - 2) & 1]) + ks * 256 + lane;
                float4* d4 = (float4*)sH1 + ks * 256 + lane;
#pragma unroll
                for (int j = 0; j < 8; j++) d4[j * 32] = __ldcg(s4 + j * 32);
            }
            __syncwarp();
        }

        // ---- L0 GEMM: R0 (regs) x h0, 64 k ----
        if (t < T_STEPS) {
            unsigned long long acc[8];
#pragma unroll
            for (int j = 0; j < 8; j++) acc[j] = 0ull;
            const float* hk = sH0 + ks * 1024;
#pragma unroll 8
            for (int k = 0; k < 64; k++) {
                unsigned long long rp = pack2(Rreg[k]);
                const unsigned long long* hp = (const unsigned long long*)(hk + k * 16);
                ulonglong2 h01 = *(const ulonglong2*)(hp + 0);
                ulonglong2 h23 = *(const ulonglong2*)(hp + 2);
                ulonglong2 h45 = *(const ulonglong2*)(hp + 4);
                ulonglong2 h67 = *(const ulonglong2*)(hp + 6);
                fma2(acc[0], rp, h01.x); fma2(acc[1], rp, h01.y);
                fma2(acc[2], rp, h23.x); fma2(acc[3], rp, h23.y);
                fma2(acc[4], rp, h45.x); fma2(acc[5], rp, h45.y);
                fma2(acc[6], rp, h67.x); fma2(acc[7], rp, h67.y);
            }
            float* pp = sP0 + ks * PS + lane * 18;
#pragma unroll
            for (int j = 0; j < 8; j++)
                *(unsigned long long*)(pp + j * 2) = acc[j];
        }

        // ---- L1 GEMM: W1 (stream) x h0  +  R1 (stream) x h1, 64 k ----
        if (t >= 1) {
            unsigned long long acc[8];
#pragma unroll
            for (int j = 0; j < 8; j++) acc[j] = 0ull;
            const float* h0k = sH0 + ks * 1024;
            const float* h1k = sH1 + ks * 1024;
#pragma unroll 2
            for (int k4 = 0; k4 < 16; k4++) {
                float4 wv = __ldg(w1p + k4 * 32);
                float4 rv = __ldg(r1p + k4 * 32);
                int kb = k4 * 4;
#define DOK(WF, RF, KK) { \
                unsigned long long wpk = pack2(WF), rpk = pack2(RF); \
                const unsigned long long* p0 = (const unsigned long long*)(h0k + (KK) * 16); \
                const unsigned long long* p1 = (const unsigned long long*)(h1k + (KK) * 16); \
                ulonglong2 a01 = *(const ulonglong2*)(p0 + 0); \
                ulonglong2 a23 = *(const ulonglong2*)(p0 + 2); \
                ulonglong2 a45 = *(const ulonglong2*)(p0 + 4); \
                ulonglong2 a67 = *(const ulonglong2*)(p0 + 6); \
                fma2(acc[0], wpk, a01.x); fma2(acc[1], wpk, a01.y); \
                fma2(acc[2], wpk, a23.x); fma2(acc[3], wpk, a23.y); \
                fma2(acc[4], wpk, a45.x); fma2(acc[5], wpk, a45.y); \
                fma2(acc[6], wpk, a67.x); fma2(acc[7], wpk, a67.y); \
                ulonglong2 b01 = *(const ulonglong2*)(p1 + 0); \
                ulonglong2 b23 = *(const ulonglong2*)(p1 + 2); \
                ulonglong2 b45 = *(const ulonglong2*)(p1 + 4); \
                ulonglong2 b67 = *(const ulonglong2*)(p1 + 6); \
                fma2(acc[0], rpk, b01.x); fma2(acc[1], rpk, b01.y); \
                fma2(acc[2], rpk, b23.x); fma2(acc[3], rpk, b23.y); \
                fma2(acc[4], rpk, b45.x); fma2(acc[5], rpk, b45.y); \
                fma2(acc[6], rpk, b67.x); fma2(acc[7], rpk, b67.y); }
                DOK(wv.x, rv.x, kb + 0)
                DOK(wv.y, rv.y, kb + 1)
                DOK(wv.z, rv.z, kb + 2)
                DOK(wv.w, rv.w, kb + 3)
#undef DOK
            }
            float* pp = sP1 + ks * PS + lane * 18;
#pragma unroll
            for (int j = 0; j < 8; j++)
                *(unsigned long long*)(pp + j * 2) = acc[j];
        }

        __syncthreads();   // BAR_A: all partials ready

        // ---- parallel pointwise: warps 0-3 = L0, warps 4-7 = L1 ----
        if (pw_grp == 0 && tid < 128) {
            if (t < T_STEPS) {
                float pre[4];
#pragma unroll
                for (int g = 0; g < 4; g++) {
                    float s = xpre[g];
                    const float* qp = sP0 + (g * 8 + pu) * 18 + pb;
#pragma unroll
                    for (int k2 = 0; k2 < 16; k2++) s += qp[k2 * PS];
                    pre[g] = s;
                }
                float ez = __expf(2.f * pre[0]);
                float z = __fdividef(ez - 1.f, ez + 1.f);
                float o = __fdividef(1.f, 1.f + __expf(-pre[3]));
                float mn = fmaxf(pre[2] + m0v, pre[1]);
                float ip = __expf(pre[1] - mn);
                float fp = __expf(pre[2] + m0v - mn);
                c0 = fp * c0 + ip * z;
                n0v = fp * n0v + ip;
                m0v = mn;
                float h = o * __fdividef(c0, n0v);
                g_hbuf0[t & 1][(u_base + pu) * 16 + pb] = h;
                asm volatile("bar.sync 1, 128;" ::: "memory");
                if (tid == 0) {
                    __threadfence();
                    g_flags0[blockIdx.x * 8] = t + 1;
                }
            }
        } else if (pw_grp == 1) {
            if (t >= 1) {
                float pre[4];
#pragma unroll
                for (int g = 0; g < 4; g++) {
                    float s = b1r[g];
                    const float* qp = sP1 + (g * 8 + pu) * 18 + pb;
#pragma unroll
                    for (int k2 = 0; k2 < 16; k2++) s += qp[k2 * PS];
                    pre[g] = s;
                }
                float ez = __expf(2.f * pre[0]);
                float z = __fdividef(ez - 1.f, ez + 1.f);
                float o = __fdividef(1.f, 1.f + __expf(-pre[3]));
                float mn = fmaxf(pre[2] + m1v, pre[1]);
                float ip = __expf(pre[1] - mn);
                float fp = __expf(pre[2] + m1v - mn);
                c1 = fp * c1 + ip * z;
                n1v = fp * n1v + ip;
                m1v = mn;
                float h = o * __fdividef(c1, n1v);
                g_hbuf1[(t - 1) & 1][(u_base + pu) * 16 + pb] = h;
                asm volatile("bar.sync 2, 128;" ::: "memory");
                if (tid == 128) {
                    __threadfence();
                    g_flags1[blockIdx.x * 8] = t;
                }
            }
        }
        __syncthreads();   // BAR_B: partials consumed, safe to overwrite
    }
}

// ===================================================================
// Final projection: h1_1023 in g_hbuf1[1023 & 1] = g_hbuf1[1]
// ===================================================================
__global__ __launch_bounds__(256) void final_out(
    const float* __restrict__ Wout, const float* __restrict__ bout,
    float* __restrict__ out)
{
    const float* hsrc = g_hbuf1[(T_STEPS - 1) & 1];
    int o = (blockIdx.x * blockDim.x + threadIdx.x) >> 5;
    int lane = threadIdx.x & 31;
    const float* wr = Wout + (size_t)o * 1024;
    float acc[16];
#pragma unroll
    for (int b = 0; b < 16; b++) acc[b] = 0.f;
    for (int k = lane; k < 1024; k += 32) {
        float w = wr[k];
        const float4* hp = (const float4*)(hsrc + k * 16);
        float4 h0 = hp[0], h1 = hp[1], h2 = hp[2], h3 = hp[3];
        acc[0]  += w * h0.x; acc[1]  += w * h0.y; acc[2]  += w * h0.z; acc[3]  += w * h0.w;
        acc[4]  += w * h1.x; acc[5]  += w * h1.y; acc[6]  += w * h1.z; acc[7]  += w * h1.w;
        acc[8]  += w * h2.x; acc[9]  += w * h2.y; acc[10] += w * h2.z; acc[11] += w * h2.w;
        acc[12] += w * h3.x; acc[13] += w * h3.y; acc[14] += w * h3.z; acc[15] += w * h3.w;
    }
#pragma unroll
    for (int b = 0; b < 16; b++) {
#pragma unroll
        for (int off = 16; off; off >>= 1)
            acc[b] += __shfl_down_sync(0xffffffffu, acc[b], off);
    }
    if (lane == 0) {
        float bo = bout[o];
#pragma unroll
        for (int b = 0; b < 16; b++)
            out[(size_t)b * 1024 + o] = acc[b] + bo;
    }
}

// ===================================================================
extern "C" void kernel_launch(void* const* d_in, const int* in_sizes, int n_in,
                              void* d_out, int out_size)
{
    const float* x    = (const float*)d_in[0];
    const float* W    = (const float*)d_in[1];
    const float* R    = (const float*)d_in[2];
    const float* bias = (const float*)d_in[3];
    const float* Wout = (const float*)d_in[4];
    const float* bout = (const float*)d_in[5];
    float* out = (float*)d_out;

    const int REC_SMEM = (32768 + 2 * 16 * PS) * 4;   // 205,824 B (~201 KB)
    cudaFuncSetAttribute(fused_rec, cudaFuncAttributeMaxDynamicSharedMemorySize, REC_SMEM);

    __nv_bfloat16 *ga3, *gw3;
    float4 *gw1p, *gr1p;
    cudaGetSymbolAddress((void**)&ga3, g_A3);
    cudaGetSymbolAddress((void**)&gw3, g_W3);
    cudaGetSymbolAddress((void**)&gw1p, g_W1p);
    cudaGetSymbolAddress((void**)&gr1p, g_R1p);

    dim3 tgrid(32, 128);
    // layer-0 xproj prep + GEMM; layer-1 weight prepack
    split3<<<4096, 256>>>(W, gw3, 1024, 2048, 0);
    split3<<<16384, 256>>>(x, ga3, 2048, 1024, 1);
    prepack<<<4096, 256>>>(W + (size_t)4096 * 1024, gw1p);
    prepack<<<4096, 256>>>(R + (size_t)4096 * 1024, gr1p);
    hmma_gemm<<<tgrid, 256>>>(bias, 0);
    // fused 2-layer recurrence
    fused_rec<<<NCTA, 512, REC_SMEM>>>(R, bias + 4096);
    // output projection
    final_out<<<128, 256>>>(Wout, bout, out);
}